// round 2
// baseline (speedup 1.0000x reference)
#include <cuda_runtime.h>
#include <math.h>

// Differentiable JPEG forward, fully fused: one CTA per 16x16 RGB tile.
// Tile = 4 Y 8x8 blocks + 1 pooled Cb 8x8 + 1 pooled Cr 8x8.
// 384 threads = 6 groups of 64; group g handles 8x8 block g through the
// separable DCT -> poly_round quant/dequant -> separable IDCT pipeline.

__constant__ float cQTY[64] = {
  16,11,10,16,24,40,51,61,
  12,12,14,19,26,58,60,55,
  14,13,16,24,40,57,69,56,
  14,17,22,29,51,87,80,62,
  18,22,37,56,68,109,103,77,
  24,35,55,64,81,104,113,92,
  49,64,78,87,103,121,120,101,
  72,92,95,98,112,100,103,99};

__constant__ float cQTC[64] = {
  17,18,24,47,99,99,99,99,
  18,21,26,66,99,99,99,99,
  24,26,56,99,99,99,99,99,
  47,66,99,99,99,99,99,99,
  99,99,99,99,99,99,99,99,
  99,99,99,99,99,99,99,99,
  99,99,99,99,99,99,99,99,
  99,99,99,99,99,99,99,99};

__device__ __forceinline__ float poly_round_f(float x) {
  float r = rintf(x);          // round-half-to-even, matches jnp.round
  float d = x - r;
  return r + d * d * d;
}
__device__ __forceinline__ float poly_floor_f(float x) {
  return poly_round_f(x - 0.5f);
}
__device__ __forceinline__ float diff_clip_f(float x, float lo, float hi) {
  float out = x;
  if (x > hi) out = -0.02f * (expf(hi - x) - 1.0f) + hi;
  if (x < lo) out =  0.02f * (expf(x - lo) - 1.0f) + lo;
  return out;
}

__global__ __launch_bounds__(384)
void jpeg_fused(const float* __restrict__ in, float* __restrict__ out) {
  const int  W     = 512;
  const long plane = 512L * 512L;

  const int t  = threadIdx.x;
  const int tx = blockIdx.x;   // tile col  0..31
  const int ty = blockIdx.y;   // tile row  0..31
  const int b  = blockIdx.z;   // batch

  __shared__ float blk[6][64];     // 6 working 8x8 blocks
  __shared__ float tmpS[6][64];    // separable-transform temporaries
  __shared__ float cbcr[2][256];   // full-res Cb/Cr before pooling
  __shared__ float Ct[64];         // Ct[u*8+x] = cos((2x+1)*u*pi/16)
  __shared__ float qtS[2][64];     // scaled quant tables (Y, C)

  const float* basep = in + (long)b * 3 * plane + (long)(ty * 16) * W + tx * 16;

  if (t < 256) {
    // ---- load one pixel, clip, scale to [0,255], RGB->YCbCr ----
    int i = t >> 4, j = t & 15;
    const float* p = basep + (long)i * W + j;
    float r  = p[0];
    float g  = p[plane];
    float bl = p[2 * plane];
    r  = fminf(fmaxf(r,  -1.0f), 1.0f);
    g  = fminf(fmaxf(g,  -1.0f), 1.0f);
    bl = fminf(fmaxf(bl, -1.0f), 1.0f);
    r  = (r  + 1.0f) * 255.0f / 2.0f;
    g  = (g  + 1.0f) * 255.0f / 2.0f;
    bl = (bl + 1.0f) * 255.0f / 2.0f;
    float Y  =  0.299f    * r + 0.587f    * g + 0.114f    * bl;
    float Cb = -0.168736f * r - 0.331264f * g + 0.5f      * bl + 128.0f;
    float Cr =  0.5f      * r - 0.418688f * g - 0.081312f * bl + 128.0f;
    int q = ((i >> 3) << 1) | (j >> 3);        // which Y quadrant
    blk[q][(i & 7) * 8 + (j & 7)] = Y - 128.0f;
    cbcr[0][t] = Cb;
    cbcr[1][t] = Cr;
  } else if (t < 320) {
    // ---- DCT basis table ----
    int e = t - 256;
    int u = e >> 3, x = e & 7;
    Ct[e] = cospif((float)((2 * x + 1) * u) * (1.0f / 16.0f));
  } else {
    // ---- scaled quant tables (q=50 -> s = poly_floor(100) = 99.875 exact) ----
    int e = t - 320;
    const float s = 99.875f;
    float tq = poly_floor_f((cQTY[e] * s + 50.0f) / 100.0f);
    qtS[0][e] = diff_clip_f(tq, 1.0f, 255.0f);
    tq = poly_floor_f((cQTC[e] * s + 50.0f) / 100.0f);
    qtS[1][e] = diff_clip_f(tq, 1.0f, 255.0f);
  }
  __syncthreads();

  // ---- 2x2 avgpool of Cb/Cr into blocks 4,5 ----
  if (t < 128) {
    int c = t >> 6, e = t & 63;
    int i = e >> 3, j = e & 7;
    const float* cc = cbcr[c];
    float v = (cc[(2 * i) * 16 + 2 * j]     + cc[(2 * i) * 16 + 2 * j + 1]
             + cc[(2 * i + 1) * 16 + 2 * j] + cc[(2 * i + 1) * 16 + 2 * j + 1]) * 0.25f;
    blk[4 + c][e] = v - 128.0f;
  }
  __syncthreads();

  const int g  = t >> 6;   // block group 0..5
  const int e  = t & 63;
  const int r0 = e >> 3;   // row index of this thread's element
  const int c0 = e & 7;    // col index

  // ---- Stage A: tmp[u][y] = sum_x blk[x][y] * C[u][x]   (u=r0, y=c0) ----
  {
    float s = 0.0f;
    #pragma unroll
    for (int x = 0; x < 8; x++) s = fmaf(blk[g][x * 8 + c0], Ct[r0 * 8 + x], s);
    tmpS[g][e] = s;
  }
  __syncthreads();

  // ---- Stage B: F[u][v] -> quant -> dequant -> fold alpha2 for IDCT ----
  {
    float s = 0.0f;
    #pragma unroll
    for (int y = 0; y < 8; y++) s = fmaf(tmpS[g][r0 * 8 + y], Ct[c0 * 8 + y], s);
    float a2 = (r0 == 0) ? ((c0 == 0) ? 0.5f : 0.70710678118654752f)
                         : ((c0 == 0) ? 0.70710678118654752f : 1.0f);
    float F = (a2 * 0.25f) * s;                 // ALPHA2*0.25 * einsum
    float q = qtS[(g < 4) ? 0 : 1][e];
    float c = poly_round_f(F / q);              // quantize
    blk[g][e] = (c * q) * a2;                   // dequant * ALPHA2 (idct input)
  }
  __syncthreads();

  // ---- Stage C: tmp[x][v] = sum_u comp[u][v] * C[u][x]   (x=r0, v=c0) ----
  {
    float s = 0.0f;
    #pragma unroll
    for (int u = 0; u < 8; u++) s = fmaf(blk[g][u * 8 + c0], Ct[u * 8 + r0], s);
    tmpS[g][e] = s;
  }
  __syncthreads();

  // ---- Stage D: pixel[x][y] = 0.25 * sum_v tmp[x][v]*C[v][y] + 128 ----
  {
    float s = 0.0f;
    #pragma unroll
    for (int v = 0; v < 8; v++) s = fmaf(tmpS[g][r0 * 8 + v], Ct[v * 8 + c0], s);
    blk[g][e] = 0.25f * s + 128.0f;
  }
  __syncthreads();

  // ---- YCbCr->RGB (chroma nearest-upsample), diff_clip, rescale, store ----
  if (t < 256) {
    int i = t >> 4, j = t & 15;
    int q = ((i >> 3) << 1) | (j >> 3);
    float Y  = blk[q][(i & 7) * 8 + (j & 7)];
    float cb = blk[4][(i >> 1) * 8 + (j >> 1)] - 128.0f;
    float cr = blk[5][(i >> 1) * 8 + (j >> 1)] - 128.0f;
    float R  = Y + 1.402f    * cr;
    float G  = Y - 0.344136f * cb - 0.714136f * cr;
    float Bv = Y + 1.772f    * cb;
    R  = diff_clip_f(R,  0.0f, 255.0f);
    G  = diff_clip_f(G,  0.0f, 255.0f);
    Bv = diff_clip_f(Bv, 0.0f, 255.0f);
    R  = fminf(fmaxf(R  * 2.0f / 255.0f - 1.0f, -1.0f), 1.0f);
    G  = fminf(fmaxf(G  * 2.0f / 255.0f - 1.0f, -1.0f), 1.0f);
    Bv = fminf(fmaxf(Bv * 2.0f / 255.0f - 1.0f, -1.0f), 1.0f);
    float* op = out + (long)b * 3 * plane + (long)(ty * 16 + i) * W + tx * 16 + j;
    op[0]         = R;
    op[plane]     = G;
    op[2 * plane] = Bv;
  }
}

extern "C" void kernel_launch(void* const* d_in, const int* in_sizes, int n_in,
                              void* d_out, int out_size) {
  const float* in = (const float*)d_in[0];
  float* out = (float*)d_out;
  int B = in_sizes[0] / (3 * 512 * 512);
  dim3 grid(32, 32, B);
  jpeg_fused<<<grid, 384>>>(in, out);
}